// round 11
// baseline (speedup 1.0000x reference)
#include <cuda_runtime.h>

// Packed fp32x2 FMA (Blackwell sm_103a): 2x fp32 throughput vs scalar FFMA.
#define FMA2(d, a, b, c) \
    asm("fma.rn.f32x2 %0, %1, %2, %3;" : "=l"(d) : "l"(a), "l"(b), "l"(c))

// Shapes (fixed): imgs (32,3,512,512) f32; weight (512,16384) f32; bias (512);
// out (32,512) f32.
#define BATCH   32
#define KDIM    16384
#define NDIM    512
#define NSPLIT  128        // K-splits == grid size (single wave on 148 SMs)
#define KPS     16         // k-pairs per W stage (32 k)
#define NSTAGE  4          // stages per block -> KCHUNK = 128 k (64 k-pairs)
#define KP_CHUNK (KPS * NSTAGE)

// smem (u64 units):
//   As2: [64 kp][34]        (32 m + 2 pad)            = 17,408 B
//   Ws : 2 x [16 kp][512 n] (XOR-swizzled, no pad)    = 131,072 B
#define AS_STRIDE 34
#define WS_BUF    (KPS * NDIM)
#define SMEM_U64  (KP_CHUNK * AS_STRIDE + 2 * WS_BUF)
#define SMEM_BYTES (SMEM_U64 * 8)              // 148,480 B

typedef unsigned long long u64;

__device__ float g_part [NSPLIT * BATCH * NDIM];   // 8 MB   [ks][i]
__device__ float g_part2[8      * BATCH * NDIM];   // 512 KB [g][i]

__device__ __forceinline__ void cp8(u64* dst, const u64* src) {
    unsigned d = (unsigned)__cvta_generic_to_shared(dst);
    asm volatile("cp.async.ca.shared.global [%0], [%1], 8;\n" :: "r"(d), "l"(src));
}
__device__ __forceinline__ void cp_commit() {
    asm volatile("cp.async.commit_group;\n" ::: "memory");
}
template <int N> __device__ __forceinline__ void cp_wait() {
    asm volatile("cp.async.wait_group %0;\n" :: "n"(N) : "memory");
}
__device__ __forceinline__ u64 packf2(float lo, float hi) {
    u64 v;
    asm("mov.b64 %0, {%1, %2};" : "=l"(v) : "r"(__float_as_uint(lo)), "r"(__float_as_uint(hi)));
    return v;
}

// ---------------------------------------------------------------------------
// Fused feats + split-K GEMM. One block per K-chunk of 128 (= 32 ij-blocks).
// Block tile: M=32 (batch) x N=512 (full) x K=128.  512 threads.
// Thread tile: 8m x 4n over packed k-pairs (even k lane0 / odd k lane1).
// Ws smem layout: [kp][n ^ kp] (u64). The XOR swizzle makes the hot w-LDS.64
// reads conflict-free (lanes = 32 permuted-consecutive u64) while cp.async
// writes are only 2-way conflicted.
// ---------------------------------------------------------------------------
__global__ __launch_bounds__(512, 1) void fused_kernel(const float* __restrict__ img,
                                                       const float* __restrict__ Wf)
{
    extern __shared__ u64 sm[];
    u64* As2 = sm;                         // [kp][m] packed A pairs
    u64* Ws  = sm + KP_CHUNK * AS_STRIDE;  // [buf][kp][n^kp]

    const int t  = threadIdx.x;
    const int ks = blockIdx.x;
    const u64* Wu = (const u64*)Wf;             // weight as k-pairs: [n][8192]
    const long kb = (long)ks * KP_CHUNK;        // this chunk's u64 k-offset

    // cp.async mapping: lanes 0-15 cover one n-row's 16 k-pairs (128B line).
    const int ck = t & 15;     // k-pair within stage
    const int cn = t >> 4;     // 0..31 (n offset within r-slab)

    // ---- prefetch W stages 0,1 ----
#pragma unroll
    for (int s = 0; s < 2; s++) {
        u64* buf = Ws + (s & 1) * WS_BUF;
#pragma unroll
        for (int r = 0; r < 16; r++) {
            int n = r * 32 + cn;
            cp8(&buf[ck * NDIM + (n ^ ck)],
                &Wu[(long)n * (KDIM / 2) + kb + s * KPS + ck]);
        }
        cp_commit();
    }

    // ---- feats phase: 1024 units (b, ijl), 2 per thread; overlaps cp.async ----
    // Only dct[0,0:4] of each 8x8 block survives:
    //   s[l] = sum_rows X[r][l];  f_m = (1/8) * sum_l s[l]*cos(pi*m*l/4)
#pragma unroll
    for (int u0 = 0; u0 < 2; u0++) {
        int u   = t + u0 * 512;
        int b   = u >> 5;
        int ijl = u & 31;
        int ij  = ks * 32 + ijl;            // global 8x8-block index
        int i   = ij >> 6, j = ij & 63;
        const float* p = img + (long)b * 786432 + (long)(i * 8) * 512 + j * 8;

        float s0 = 0.f, s1 = 0.f, s2 = 0.f, s3 = 0.f;
        float s4 = 0.f, s5 = 0.f, s6 = 0.f, s7 = 0.f;
#pragma unroll
        for (int r = 0; r < 8; r++) {
            float4 lo = *(const float4*)(p + r * 512);
            float4 hi = *(const float4*)(p + r * 512 + 4);
            s0 += lo.x; s1 += lo.y; s2 += lo.z; s3 += lo.w;
            s4 += hi.x; s5 += hi.y; s6 += hi.z; s7 += hi.w;
        }
        const float R = 0.70710678118654752f;
        float e = s0 - s4;
        float o = s1 - s3 - s5 + s7;
        float f0 = 0.125f * (((s0 + s1) + (s2 + s3)) + ((s4 + s5) + (s6 + s7)));
        float f1 = 0.125f * (e + R * o);
        float f2 = 0.125f * ((s0 - s2) + (s4 - s6));
        float f3 = 0.125f * (e - R * o);

        As2[(2 * ijl    ) * AS_STRIDE + b] = packf2(f0, f1);   // k-pair (4ijl, 4ijl+1)
        As2[(2 * ijl + 1) * AS_STRIDE + b] = packf2(f2, f3);   // k-pair (4ijl+2, 4ijl+3)
    }
    __syncthreads();   // A ready for all stages

    // ---- output mapping: 8m x 4n per thread ----
    const int tx = t & 31;
    const int ty = t >> 5;
    const int m0 = (ty & 3) * 8;                 // 8 m rows
    const int nb = (ty >> 2) * 128 + tx;         // 4 n: nb + 32*q

    u64 acc[8][4];
#pragma unroll
    for (int mi = 0; mi < 8; mi++)
#pragma unroll
        for (int q = 0; q < 4; q++) acc[mi][q] = 0ULL;

    // ---- mainloop over 4 W stages ----
    for (int s = 0; s < NSTAGE; s++) {
        cp_wait<1>();          // stage s complete (groups retire in order)
        __syncthreads();
        const u64* buf = Ws + (s & 1) * WS_BUF;

#pragma unroll
        for (int kpl = 0; kpl < KPS; kpl++) {
            const u64* arow = &As2[(s * KPS + kpl) * AS_STRIDE + m0];
            ulonglong2 A01 = *(const ulonglong2*)(arow);       // broadcast LDS.128
            ulonglong2 A23 = *(const ulonglong2*)(arow + 2);
            ulonglong2 A45 = *(const ulonglong2*)(arow + 4);
            ulonglong2 A67 = *(const ulonglong2*)(arow + 6);
            u64 a[8] = {A01.x, A01.y, A23.x, A23.y, A45.x, A45.y, A67.x, A67.y};

            const u64* wrow = buf + kpl * NDIM;
            u64 w2[4];
#pragma unroll
            for (int q = 0; q < 4; q++)
                w2[q] = wrow[(nb + 32 * q) ^ kpl];   // conflict-free (swizzled)

#pragma unroll
            for (int mi = 0; mi < 8; mi++)
#pragma unroll
                for (int q = 0; q < 4; q++)
                    FMA2(acc[mi][q], a[mi], w2[q], acc[mi][q]);
        }
        __syncthreads();       // everyone done reading buf before overwrite

        if (s + 2 < NSTAGE) {  // refill this buffer with stage s+2
            u64* nbuf = Ws + (s & 1) * WS_BUF;
#pragma unroll
            for (int r = 0; r < 16; r++) {
                int n = r * 32 + cn;
                cp8(&nbuf[ck * NDIM + (n ^ ck)],
                    &Wu[(long)n * (KDIM / 2) + kb + (s + 2) * KPS + ck]);
            }
        }
        cp_commit();           // empty groups on last iters keep wait<1> aligned
    }

    // ---- fold k-pair lanes, write partials (coalesced over tx) ----
    float* outp = g_part + (long)ks * (BATCH * NDIM);
#pragma unroll
    for (int mi = 0; mi < 8; mi++) {
#pragma unroll
        for (int q = 0; q < 4; q++) {
            u64 v = acc[mi][q];
            float lo = __uint_as_float((unsigned)(v & 0xffffffffULL));
            float hi = __uint_as_float((unsigned)(v >> 32));
            outp[(m0 + mi) * NDIM + nb + 32 * q] = lo + hi;
        }
    }
}

// ---------------------------------------------------------------------------
// Split-K reduction, stage 1: 128 -> 8 partials. 131072 threads -> L2 BW bound
// instead of latency bound. Deterministic fixed-order sums.
// ---------------------------------------------------------------------------
__global__ __launch_bounds__(256) void reduce1_kernel()
{
    int tid = blockIdx.x * 256 + threadIdx.x;   // 0 .. 131071
    int g = tid >> 14;                           // group 0..7 (16 splits each)
    int i = tid & (BATCH * NDIM - 1);            // output index 0..16383

    const float* p = g_part + (long)(g * 16) * (BATCH * NDIM) + i;
    float a0 = 0.f, a1 = 0.f, a2 = 0.f, a3 = 0.f;
#pragma unroll
    for (int j = 0; j < 16; j += 4) {
        a0 += p[(long)(j + 0) * (BATCH * NDIM)];
        a1 += p[(long)(j + 1) * (BATCH * NDIM)];
        a2 += p[(long)(j + 2) * (BATCH * NDIM)];
        a3 += p[(long)(j + 3) * (BATCH * NDIM)];
    }
    g_part2[(long)g * (BATCH * NDIM) + i] = (a0 + a1) + (a2 + a3);
}

// ---------------------------------------------------------------------------
// Split-K reduction, stage 2: 8 -> 1, plus bias.
// ---------------------------------------------------------------------------
__global__ __launch_bounds__(256) void reduce2_kernel(const float* __restrict__ bias,
                                                      float* __restrict__ out)
{
    int i = blockIdx.x * 256 + threadIdx.x;   // 0 .. 16383
    float a0 = 0.f, a1 = 0.f, a2 = 0.f, a3 = 0.f;
#pragma unroll
    for (int g = 0; g < 8; g += 4) {
        a0 += g_part2[(long)(g + 0) * (BATCH * NDIM) + i];
        a1 += g_part2[(long)(g + 1) * (BATCH * NDIM) + i];
        a2 += g_part2[(long)(g + 2) * (BATCH * NDIM) + i];
        a3 += g_part2[(long)(g + 3) * (BATCH * NDIM) + i];
    }
    out[i] = ((a0 + a1) + (a2 + a3)) + bias[i & (NDIM - 1)];
}

// ---------------------------------------------------------------------------
extern "C" void kernel_launch(void* const* d_in, const int* in_sizes, int n_in,
                              void* d_out, int out_size)
{
    const float* img    = (const float*)d_in[0];
    const float* weight = (const float*)d_in[1];
    const float* bias   = (const float*)d_in[2];
    float* out = (float*)d_out;

    cudaFuncSetAttribute(fused_kernel,
                         cudaFuncAttributeMaxDynamicSharedMemorySize, SMEM_BYTES);

    fused_kernel<<<NSPLIT, 512, SMEM_BYTES>>>(img, weight);
    reduce1_kernel<<<512, 256>>>();
    reduce2_kernel<<<(BATCH * NDIM) / 256, 256>>>(bias, out);
}

// round 13
// speedup vs baseline: 1.4264x; 1.4264x over previous
#include <cuda_runtime.h>
#include <cuda_bf16.h>
#include <cstdint>

typedef unsigned long long u64;
typedef unsigned int u32;

// Shapes (fixed): imgs (32,3,512,512) f32; weight (512,16384) f32; bias (512);
// out (32,512) f32.
#define BATCH    32
#define NDIM     512
#define KDIM     16384
#define KSPLIT   32         // GEMM grid.y
#define KCHUNK   512        // k per CTA
#define KSTAGE   64         // k per W pipeline stage
#define NSTAGES  8          // KCHUNK / KSTAGE
#define MTILE    128        // W rows per CTA

// smem strides (bank-conflict-free for the mma fragment access pattern)
#define WSTRIDE  72                     // f32 per W row   (4*row + tg distinct mod 32)
#define WSTAGE_F (MTILE * WSTRIDE)      // 9216 f32 = 36864 B per stage
#define BSTRIDE  520                    // bf16 per B row  (4*g + tg distinct mod 32)
#define SMEM_W_BYTES (2 * WSTAGE_F * 4)              // 73728
#define SMEM_B_BYTES (BATCH * BSTRIDE * 2)           // 33280 per (hi|lo)
#define SMEM_BYTES (SMEM_W_BYTES + 2 * SMEM_B_BYTES) // 140288

// Device scratch (no allocation allowed anywhere)
__device__ __align__(256) __nv_bfloat16 g_fhi[BATCH * KDIM];  // 1 MB feats hi
__device__ __align__(256) __nv_bfloat16 g_flo[BATCH * KDIM];  // 1 MB feats lo
__device__ float g_part [KSPLIT * NDIM * BATCH];              // 2 MB [ks][nout][b]
__device__ float g_part2[4 * NDIM * BATCH];                   // 256 KB

// ---------------------------------------------------------------------------
// PTX helpers (baseline features only — compute_103 virtual arch, no 'a')
// ---------------------------------------------------------------------------
__device__ __forceinline__ void cp16(void* dst, const void* src) {
    u32 d = (u32)__cvta_generic_to_shared(dst);
    asm volatile("cp.async.ca.shared.global [%0], [%1], 16;\n"
                 :: "r"(d), "l"(src) : "memory");
}
__device__ __forceinline__ void cp_commit() {
    asm volatile("cp.async.commit_group;\n" ::: "memory");
}
template <int N> __device__ __forceinline__ void cp_wait() {
    asm volatile("cp.async.wait_group %0;\n" :: "n"(N) : "memory");
}
// pack two f32 -> bf16x2 reg {lo = v.x, hi = v.y}
__device__ __forceinline__ u32 bf2hi(float2 v) {
    u32 d;
    asm("cvt.rn.bf16x2.f32 %0, %1, %2;" : "=r"(d) : "f"(v.y), "f"(v.x));
    return d;
}
// residual (lo) pair given the hi pair
__device__ __forceinline__ u32 bf2lo(float2 v, u32 h) {
    float h0 = __uint_as_float(h << 16);
    float h1 = __uint_as_float(h & 0xffff0000u);
    float l0 = v.x - h0, l1 = v.y - h1;
    u32 d;
    asm("cvt.rn.bf16x2.f32 %0, %1, %2;" : "=r"(d) : "f"(l1), "f"(l0));
    return d;
}
__device__ __forceinline__ void mma16816(float* c, u32 a0, u32 a1, u32 a2, u32 a3,
                                         u32 b0, u32 b1) {
    asm volatile(
        "mma.sync.aligned.m16n8k16.row.col.f32.bf16.bf16.f32 "
        "{%0,%1,%2,%3}, {%4,%5,%6,%7}, {%8,%9}, {%0,%1,%2,%3};"
        : "+f"(c[0]), "+f"(c[1]), "+f"(c[2]), "+f"(c[3])
        : "r"(a0), "r"(a1), "r"(a2), "r"(a3), "r"(b0), "r"(b1));
}
__device__ __forceinline__ u64 pack4(__nv_bfloat16 a, __nv_bfloat16 b,
                                     __nv_bfloat16 c, __nv_bfloat16 d) {
    return (u64)__bfloat16_as_ushort(a)
         | ((u64)__bfloat16_as_ushort(b) << 16)
         | ((u64)__bfloat16_as_ushort(c) << 32)
         | ((u64)__bfloat16_as_ushort(d) << 48);
}
__device__ __forceinline__ void split1(float f, __nv_bfloat16& h, __nv_bfloat16& l) {
    h = __float2bfloat16(f);
    l = __float2bfloat16(f - __bfloat162float(h));
}

// ---------------------------------------------------------------------------
// Kernel 1: DCT features -> bf16 hi/lo planes [b][k], k = ij*4 + m.
// Only dct[0,0:4] survives:  s[l] = col-sums;  f_m = (1/8)*sum_l s[l]*cos(pi m l/4).
// 2 threads per 8x8 block: half=0 sums cols 0-3, half=1 cols 4-7 (coalesced
// LDG.128), combined via shfl_xor(1); both halves compute f0..f3, then half0
// stores the hi 4-pack and half1 the lo 4-pack (8B u64 stores).
// ---------------------------------------------------------------------------
__global__ __launch_bounds__(256) void feats_kernel(const float* __restrict__ img)
{
    int tid  = blockIdx.x * 256 + threadIdx.x;   // 0 .. 262143
    int u    = tid >> 1;
    int half = tid & 1;
    int b    = u >> 12;
    int ij   = u & 4095;
    int i = ij >> 6, j = ij & 63;

    const float* p = img + (long)b * 786432 + (long)(i * 8) * 512 + j * 8 + half * 4;

    float q0 = 0.f, q1 = 0.f, q2 = 0.f, q3 = 0.f;
#pragma unroll
    for (int r = 0; r < 8; r++) {
        float4 v = *(const float4*)(p + r * 512);
        q0 += v.x; q1 += v.y; q2 += v.z; q3 += v.w;
    }
    float c0 = (q0 + q1) + (q2 + q3);   // partial sum
    float c1 = q0;                       // s0 / s4
    float c2 = q1 - q3;                  // (s1-s3) / (s5-s7)
    float c3 = q0 - q2;                  // (s0-s2) / (s4-s6)

    float o0 = __shfl_xor_sync(0xffffffffu, c0, 1);
    float o1 = __shfl_xor_sync(0xffffffffu, c1, 1);
    float o2 = __shfl_xor_sync(0xffffffffu, c2, 1);
    float o3 = __shfl_xor_sync(0xffffffffu, c3, 1);

    float L0 = half ? o0 : c0, H0 = half ? c0 : o0;
    float L1 = half ? o1 : c1, H1 = half ? c1 : o1;
    float L2 = half ? o2 : c2, H2 = half ? c2 : o2;
    float L3 = half ? o3 : c3, H3 = half ? c3 : o3;

    const float R = 0.70710678118654752f;
    float e = L1 - H1;
    float o = L2 - H2;
    float f0 = 0.125f * (L0 + H0);
    float f1 = 0.125f * (e + R * o);
    float f2 = 0.125f * (L3 + H3);
    float f3 = 0.125f * (e - R * o);

    __nv_bfloat16 h0, l0, h1, l1, h2, l2, h3, l3;
    split1(f0, h0, l0); split1(f1, h1, l1);
    split1(f2, h2, l2); split1(f3, h3, l3);

    long idx = (long)b * KDIM + ij * 4;          // bf16 element index (8B aligned)
    if (half == 0)
        *(u64*)&g_fhi[idx] = pack4(h0, h1, h2, h3);
    else
        *(u64*)&g_flo[idx] = pack4(l0, l1, l2, l3);
}

// ---------------------------------------------------------------------------
// Kernel 2: split-K GEMM on tensor cores (mma.sync m16n8k16 bf16, HMMA path).
//   D[512 nout, 32 b] = W @ feats^T via 3-term hi/lo split (err ~1e-5).
// grid (4 m-tiles, 32 k-splits), 256 threads. B (feats hi/lo, this k-chunk)
// cp.async'd once; W fp32 double-buffered in 64-k stages, converted to bf16
// hi/lo fragments during LDS. Warp w owns m-rows [w*16, w*16+16), n = all 32.
// ---------------------------------------------------------------------------
__global__ __launch_bounds__(256, 1) void gemm_kernel(const float* __restrict__ W)
{
    extern __shared__ char sm[];
    float*         sW  = (float*)sm;                                  // [2][128][72]
    __nv_bfloat16* sBh = (__nv_bfloat16*)(sm + SMEM_W_BYTES);         // [32][520]
    __nv_bfloat16* sBl = (__nv_bfloat16*)(sm + SMEM_W_BYTES + SMEM_B_BYTES);

    const int t  = threadIdx.x;
    const int w  = t >> 5, lid = t & 31;
    const int g  = lid >> 2, tg = lid & 3;
    const int mt = blockIdx.x, ks = blockIdx.y;

    const float* Wbase = W + (size_t)(mt * MTILE) * KDIM + ks * KCHUNK;

    // ---- B chunk (hi+lo, 32 x 512 bf16 each): one-shot cp.async ----
#pragma unroll
    for (int i = 0; i < 8; i++) {
        int idx = t + i * 256;             // 0..2047 -> 16B chunks
        int br = idx >> 6, c = idx & 63;   // row, 8-bf16 chunk
        long src = (long)br * KDIM + ks * KCHUNK + c * 8;
        cp16(&sBh[br * BSTRIDE + c * 8], &g_fhi[src]);
        cp16(&sBl[br * BSTRIDE + c * 8], &g_flo[src]);
    }
    // ---- W stage 0 into group 0 (with B), stage 1 into group 1 ----
#pragma unroll
    for (int i = 0; i < 8; i++) {
        int idx = t + i * 256;             // 0..2047
        int row = idx >> 4, c4 = idx & 15;
        cp16(&sW[row * WSTRIDE + c4 * 4],
             Wbase + (size_t)row * KDIM + c4 * 4);
    }
    cp_commit();                           // group 0: B + W0
#pragma unroll
    for (int i = 0; i < 8; i++) {
        int idx = t + i * 256;
        int row = idx >> 4, c4 = idx & 15;
        cp16(&sW[WSTAGE_F + row * WSTRIDE + c4 * 4],
             Wbase + (size_t)row * KDIM + KSTAGE + c4 * 4);
    }
    cp_commit();                           // group 1: W1

    float acc[4][4];
#pragma unroll
    for (int q = 0; q < 4; q++)
#pragma unroll
        for (int r = 0; r < 4; r++) acc[q][r] = 0.f;

    const int wr = w * 16;

    for (int s = 0; s < NSTAGES; s++) {
        if (s + 1 < NSTAGES) cp_wait<1>(); else cp_wait<0>();
        __syncthreads();
        const float* sWb = sW + (s & 1) * WSTAGE_F;

#pragma unroll
        for (int k16 = 0; k16 < KSTAGE / 16; k16++) {
            const int k0  = k16 * 16;
            const int kk0 = s * KSTAGE + k0;    // B index within chunk

            // A fragments: fp32 pairs -> bf16 hi/lo
            float2 w00 = *(const float2*)&sWb[(wr + g    ) * WSTRIDE + k0 + tg * 2];
            float2 w01 = *(const float2*)&sWb[(wr + g + 8) * WSTRIDE + k0 + tg * 2];
            float2 w10 = *(const float2*)&sWb[(wr + g    ) * WSTRIDE + k0 + tg * 2 + 8];
            float2 w11 = *(const float2*)&sWb[(wr + g + 8) * WSTRIDE + k0 + tg * 2 + 8];
            u32 ah0 = bf2hi(w00), ah1 = bf2hi(w01), ah2 = bf2hi(w10), ah3 = bf2hi(w11);
            u32 al0 = bf2lo(w00, ah0), al1 = bf2lo(w01, ah1);
            u32 al2 = bf2lo(w10, ah2), al3 = bf2lo(w11, ah3);

#pragma unroll
            for (int q = 0; q < 4; q++) {
                const __nv_bfloat16* bh = &sBh[(q * 8 + g) * BSTRIDE + kk0 + tg * 2];
                const __nv_bfloat16* bl = &sBl[(q * 8 + g) * BSTRIDE + kk0 + tg * 2];
                u32 bh0 = *(const u32*)(bh);
                u32 bh1 = *(const u32*)(bh + 8);
                u32 bl0 = *(const u32*)(bl);
                u32 bl1 = *(const u32*)(bl + 8);

                mma16816(acc[q], ah0, ah1, ah2, ah3, bh0, bh1);  // hi*hi
                mma16816(acc[q], ah0, ah1, ah2, ah3, bl0, bl1);  // hi*lo
                mma16816(acc[q], al0, al1, al2, al3, bh0, bh1);  // lo*hi
            }
        }
        __syncthreads();   // all warps done with sWb before refill

        if (s + 2 < NSTAGES) {
            float* dst = sW + (s & 1) * WSTAGE_F;
            const float* src = Wbase + (size_t)(s + 2) * KSTAGE;
#pragma unroll
            for (int i = 0; i < 8; i++) {
                int idx = t + i * 256;
                int row = idx >> 4, c4 = idx & 15;
                cp16(&dst[row * WSTRIDE + c4 * 4],
                     src + (size_t)row * KDIM + c4 * 4);
            }
            cp_commit();
        }
    }

    // ---- epilogue: g_part[ks][nout][batch]; c0/c1 and c2/c3 are batch-adjacent
    float* op = g_part + (long)ks * (NDIM * BATCH);
    int nout = mt * MTILE + wr + g;
#pragma unroll
    for (int q = 0; q < 4; q++) {
        int bcol = q * 8 + tg * 2;
        *(float2*)&op[(long)nout * BATCH + bcol]       = make_float2(acc[q][0], acc[q][1]);
        *(float2*)&op[(long)(nout + 8) * BATCH + bcol] = make_float2(acc[q][2], acc[q][3]);
    }
}

// ---------------------------------------------------------------------------
// Split-K reduce, stage 1: 32 -> 4 (65536 threads, L2-BW bound, deterministic)
// ---------------------------------------------------------------------------
__global__ __launch_bounds__(256) void reduce1_kernel()
{
    int tid = blockIdx.x * 256 + threadIdx.x;   // 0 .. 65535
    int gg = tid >> 14;                          // group 0..3 (8 splits each)
    int i  = tid & (NDIM * BATCH - 1);

    const float* p = g_part + (long)(gg * 8) * (NDIM * BATCH) + i;
    float a0 = p[0]                       + p[(long)1 * NDIM * BATCH];
    float a1 = p[(long)2 * NDIM * BATCH]  + p[(long)3 * NDIM * BATCH];
    float a2 = p[(long)4 * NDIM * BATCH]  + p[(long)5 * NDIM * BATCH];
    float a3 = p[(long)6 * NDIM * BATCH]  + p[(long)7 * NDIM * BATCH];
    g_part2[(long)gg * (NDIM * BATCH) + i] = (a0 + a1) + (a2 + a3);
}

// ---------------------------------------------------------------------------
// Split-K reduce, stage 2: 4 -> 1, bias, transpose [nout][b] -> out[b][nout].
// ---------------------------------------------------------------------------
__global__ __launch_bounds__(256) void reduce2_kernel(const float* __restrict__ bias,
                                                      float* __restrict__ out)
{
    int i = blockIdx.x * 256 + threadIdx.x;     // 0 .. 16383 = nout*32 + b
    int nout = i >> 5, b = i & 31;
    float a0 = g_part2[i]                         + g_part2[(long)1 * NDIM * BATCH + i];
    float a1 = g_part2[(long)2 * NDIM * BATCH + i] + g_part2[(long)3 * NDIM * BATCH + i];
    out[b * NDIM + nout] = (a0 + a1) + bias[nout];
}

// ---------------------------------------------------------------------------
extern "C" void kernel_launch(void* const* d_in, const int* in_sizes, int n_in,
                              void* d_out, int out_size)
{
    const float* img    = (const float*)d_in[0];
    const float* weight = (const float*)d_in[1];
    const float* bias   = (const float*)d_in[2];
    float* out = (float*)d_out;

    cudaFuncSetAttribute(gemm_kernel,
                         cudaFuncAttributeMaxDynamicSharedMemorySize, SMEM_BYTES);

    feats_kernel<<<1024, 256>>>(img);
    gemm_kernel<<<dim3(4, KSPLIT), 256, SMEM_BYTES>>>(weight);
    reduce1_kernel<<<256, 256>>>();
    reduce2_kernel<<<(NDIM * BATCH) / 256, 256>>>(bias, out);
}

// round 14
// speedup vs baseline: 1.5333x; 1.0750x over previous
#include <cuda_runtime.h>
#include <cuda_bf16.h>
#include <cstdint>

typedef unsigned long long u64;
typedef unsigned int u32;

// Shapes (fixed): imgs (32,3,512,512) f32; weight (512,16384) f32; bias (512);
// out (32,512) f32.
#define BATCH    32
#define NDIM     512
#define KDIM     16384
#define KSPLIT   32         // GEMM grid.y
#define KCHUNK   512        // k per CTA
#define KSTAGE   64         // k per W pipeline stage
#define NSTAGES  8          // KCHUNK / KSTAGE
#define MTILE    128        // W rows per CTA
#define NWBUF    3          // W pipeline depth (triple buffer)

// smem strides (bank-conflict-free for the mma fragment access pattern)
#define WSTRIDE  72                     // f32 per W row
#define WSTAGE_F (MTILE * WSTRIDE)      // 9216 f32 = 36864 B per stage
#define BSTRIDE  520                    // bf16 per B row
#define SMEM_W_BYTES (NWBUF * WSTAGE_F * 4)          // 110592
#define SMEM_B_BYTES (BATCH * BSTRIDE * 2)           // 33280 per (hi|lo)
#define SMEM_BYTES (SMEM_W_BYTES + 2 * SMEM_B_BYTES) // 177152

// Device scratch (no allocation allowed anywhere)
__device__ __align__(256) __nv_bfloat16 g_fhi[BATCH * KDIM];  // 1 MB feats hi
__device__ __align__(256) __nv_bfloat16 g_flo[BATCH * KDIM];  // 1 MB feats lo
__device__ float g_part[KSPLIT * NDIM * BATCH];               // 2 MB [ks][nout][b]

// ---------------------------------------------------------------------------
// PTX helpers (baseline features only — compute_103 virtual arch, no 'a')
// ---------------------------------------------------------------------------
__device__ __forceinline__ void cp16(void* dst, const void* src) {
    u32 d = (u32)__cvta_generic_to_shared(dst);
    asm volatile("cp.async.ca.shared.global [%0], [%1], 16;\n"
                 :: "r"(d), "l"(src) : "memory");
}
__device__ __forceinline__ void cp_commit() {
    asm volatile("cp.async.commit_group;\n" ::: "memory");
}
template <int N> __device__ __forceinline__ void cp_wait() {
    asm volatile("cp.async.wait_group %0;\n" :: "n"(N) : "memory");
}
// pack two f32 -> bf16x2 reg {lo = v.x, hi = v.y}
__device__ __forceinline__ u32 bf2hi(float2 v) {
    u32 d;
    asm("cvt.rn.bf16x2.f32 %0, %1, %2;" : "=r"(d) : "f"(v.y), "f"(v.x));
    return d;
}
// residual (lo) pair given the hi pair
__device__ __forceinline__ u32 bf2lo(float2 v, u32 h) {
    float h0 = __uint_as_float(h << 16);
    float h1 = __uint_as_float(h & 0xffff0000u);
    float l0 = v.x - h0, l1 = v.y - h1;
    u32 d;
    asm("cvt.rn.bf16x2.f32 %0, %1, %2;" : "=r"(d) : "f"(l1), "f"(l0));
    return d;
}
__device__ __forceinline__ void mma16816(float* c, u32 a0, u32 a1, u32 a2, u32 a3,
                                         u32 b0, u32 b1) {
    asm volatile(
        "mma.sync.aligned.m16n8k16.row.col.f32.bf16.bf16.f32 "
        "{%0,%1,%2,%3}, {%4,%5,%6,%7}, {%8,%9}, {%0,%1,%2,%3};"
        : "+f"(c[0]), "+f"(c[1]), "+f"(c[2]), "+f"(c[3])
        : "r"(a0), "r"(a1), "r"(a2), "r"(a3), "r"(b0), "r"(b1));
}
__device__ __forceinline__ u64 pack4(__nv_bfloat16 a, __nv_bfloat16 b,
                                     __nv_bfloat16 c, __nv_bfloat16 d) {
    return (u64)__bfloat16_as_ushort(a)
         | ((u64)__bfloat16_as_ushort(b) << 16)
         | ((u64)__bfloat16_as_ushort(c) << 32)
         | ((u64)__bfloat16_as_ushort(d) << 48);
}
__device__ __forceinline__ void split1(float f, __nv_bfloat16& h, __nv_bfloat16& l) {
    h = __float2bfloat16(f);
    l = __float2bfloat16(f - __bfloat162float(h));
}

// ---------------------------------------------------------------------------
// Kernel 1: DCT features -> bf16 hi/lo planes [b][k], k = ij*4 + m.
// Only dct[0,0:4] survives:  s[l] = col-sums;  f_m = (1/8)*sum_l s[l]*cos(pi m l/4).
// 2 threads per 8x8 block (halves combined via shfl_xor(1)); half0 stores the
// hi 4-pack, half1 the lo 4-pack (8B u64 stores, fully coalesced).
// ---------------------------------------------------------------------------
__global__ __launch_bounds__(256) void feats_kernel(const float* __restrict__ img)
{
    int tid  = blockIdx.x * 256 + threadIdx.x;   // 0 .. 262143
    int u    = tid >> 1;
    int half = tid & 1;
    int b    = u >> 12;
    int ij   = u & 4095;
    int i = ij >> 6, j = ij & 63;

    const float* p = img + (long)b * 786432 + (long)(i * 8) * 512 + j * 8 + half * 4;

    float q0 = 0.f, q1 = 0.f, q2 = 0.f, q3 = 0.f;
#pragma unroll
    for (int r = 0; r < 8; r++) {
        float4 v = *(const float4*)(p + r * 512);
        q0 += v.x; q1 += v.y; q2 += v.z; q3 += v.w;
    }
    float c0 = (q0 + q1) + (q2 + q3);   // partial sum
    float c1 = q0;                       // s0 / s4
    float c2 = q1 - q3;                  // (s1-s3) / (s5-s7)
    float c3 = q0 - q2;                  // (s0-s2) / (s4-s6)

    float o0 = __shfl_xor_sync(0xffffffffu, c0, 1);
    float o1 = __shfl_xor_sync(0xffffffffu, c1, 1);
    float o2 = __shfl_xor_sync(0xffffffffu, c2, 1);
    float o3 = __shfl_xor_sync(0xffffffffu, c3, 1);

    float L0 = half ? o0 : c0, H0 = half ? c0 : o0;
    float L1 = half ? o1 : c1, H1 = half ? c1 : o1;
    float L2 = half ? o2 : c2, H2 = half ? c2 : o2;
    float L3 = half ? o3 : c3, H3 = half ? c3 : o3;

    const float R = 0.70710678118654752f;
    float e = L1 - H1;
    float o = L2 - H2;
    float f0 = 0.125f * (L0 + H0);
    float f1 = 0.125f * (e + R * o);
    float f2 = 0.125f * (L3 + H3);
    float f3 = 0.125f * (e - R * o);

    __nv_bfloat16 h0, l0, h1, l1, h2, l2, h3, l3;
    split1(f0, h0, l0); split1(f1, h1, l1);
    split1(f2, h2, l2); split1(f3, h3, l3);

    long idx = (long)b * KDIM + ij * 4;          // bf16 element index (8B aligned)
    if (half == 0)
        *(u64*)&g_fhi[idx] = pack4(h0, h1, h2, h3);
    else
        *(u64*)&g_flo[idx] = pack4(l0, l1, l2, l3);
}

// ---------------------------------------------------------------------------
// Kernel 2: split-K GEMM on tensor cores (mma.sync m16n8k16 bf16, HMMA path).
//   D[512 nout, 32 b] = W @ feats^T via 3-term hi/lo split (err ~1e-5).
// grid (4 m-tiles, 32 k-splits), 256 threads. B (feats hi/lo for this k-chunk)
// cp.async'd once; W fp32 TRIPLE-buffered in 64-k stages (load slack = 2
// compute stages), converted to bf16 hi/lo fragments during LDS.
// Warp w owns m-rows [w*16, w*16+16), n = all 32 batches.
// ---------------------------------------------------------------------------
__global__ __launch_bounds__(256, 1) void gemm_kernel(const float* __restrict__ W)
{
    extern __shared__ char sm[];
    float*         sW  = (float*)sm;                                  // [3][128][72]
    __nv_bfloat16* sBh = (__nv_bfloat16*)(sm + SMEM_W_BYTES);         // [32][520]
    __nv_bfloat16* sBl = (__nv_bfloat16*)(sm + SMEM_W_BYTES + SMEM_B_BYTES);

    const int t  = threadIdx.x;
    const int w  = t >> 5, lid = t & 31;
    const int g  = lid >> 2, tg = lid & 3;
    const int mt = blockIdx.x, ks = blockIdx.y;

    const float* Wbase = W + (size_t)(mt * MTILE) * KDIM + ks * KCHUNK;

    // ---- B chunk (hi+lo, 32 x 512 bf16 each) + W stage 0 -> group 0 ----
#pragma unroll
    for (int i = 0; i < 8; i++) {
        int idx = t + i * 256;             // 0..2047 -> 16B chunks
        int br = idx >> 6, c = idx & 63;
        long src = (long)br * KDIM + ks * KCHUNK + c * 8;
        cp16(&sBh[br * BSTRIDE + c * 8], &g_fhi[src]);
        cp16(&sBl[br * BSTRIDE + c * 8], &g_flo[src]);
    }
#pragma unroll
    for (int i = 0; i < 8; i++) {
        int idx = t + i * 256;
        int row = idx >> 4, c4 = idx & 15;
        cp16(&sW[row * WSTRIDE + c4 * 4], Wbase + (size_t)row * KDIM + c4 * 4);
    }
    cp_commit();                           // group 0: B + W0
    // ---- W stages 1,2 -> groups 1,2 ----
#pragma unroll
    for (int s = 1; s < 3; s++) {
#pragma unroll
        for (int i = 0; i < 8; i++) {
            int idx = t + i * 256;
            int row = idx >> 4, c4 = idx & 15;
            cp16(&sW[s * WSTAGE_F + row * WSTRIDE + c4 * 4],
                 Wbase + (size_t)row * KDIM + s * KSTAGE + c4 * 4);
        }
        cp_commit();
    }

    float acc[4][4];
#pragma unroll
    for (int q = 0; q < 4; q++)
#pragma unroll
        for (int r = 0; r < 4; r++) acc[q][r] = 0.f;

    const int wr = w * 16;
    int bufs = 0;   // s % 3

    for (int s = 0; s < NSTAGES; s++) {
        cp_wait<2>();          // oldest pending group (stage s) complete
        __syncthreads();
        const float* sWb = sW + bufs * WSTAGE_F;

#pragma unroll
        for (int k16 = 0; k16 < KSTAGE / 16; k16++) {
            const int k0  = k16 * 16;
            const int kk0 = s * KSTAGE + k0;    // B index within chunk

            // A fragments: fp32 pairs -> bf16 hi/lo
            float2 w00 = *(const float2*)&sWb[(wr + g    ) * WSTRIDE + k0 + tg * 2];
            float2 w01 = *(const float2*)&sWb[(wr + g + 8) * WSTRIDE + k0 + tg * 2];
            float2 w10 = *(const float2*)&sWb[(wr + g    ) * WSTRIDE + k0 + tg * 2 + 8];
            float2 w11 = *(const float2*)&sWb[(wr + g + 8) * WSTRIDE + k0 + tg * 2 + 8];
            u32 ah0 = bf2hi(w00), ah1 = bf2hi(w01), ah2 = bf2hi(w10), ah3 = bf2hi(w11);
            u32 al0 = bf2lo(w00, ah0), al1 = bf2lo(w01, ah1);
            u32 al2 = bf2lo(w10, ah2), al3 = bf2lo(w11, ah3);

#pragma unroll
            for (int q = 0; q < 4; q++) {
                const __nv_bfloat16* bh = &sBh[(q * 8 + g) * BSTRIDE + kk0 + tg * 2];
                const __nv_bfloat16* bl = &sBl[(q * 8 + g) * BSTRIDE + kk0 + tg * 2];
                u32 bh0 = *(const u32*)(bh);
                u32 bh1 = *(const u32*)(bh + 8);
                u32 bl0 = *(const u32*)(bl);
                u32 bl1 = *(const u32*)(bl + 8);

                mma16816(acc[q], ah0, ah1, ah2, ah3, bh0, bh1);  // hi*hi
                mma16816(acc[q], ah0, ah1, ah2, ah3, bl0, bl1);  // hi*lo
                mma16816(acc[q], al0, al1, al2, al3, bh0, bh1);  // lo*hi
            }
        }
        __syncthreads();   // all warps done with buf s before refill

        if (s + 3 < NSTAGES) {   // refill this buffer with stage s+3
            float* dst = sW + bufs * WSTAGE_F;
            const float* src = Wbase + (size_t)(s + 3) * KSTAGE;
#pragma unroll
            for (int i = 0; i < 8; i++) {
                int idx = t + i * 256;
                int row = idx >> 4, c4 = idx & 15;
                cp16(&dst[row * WSTRIDE + c4 * 4],
                     src + (size_t)row * KDIM + c4 * 4);
            }
        }
        cp_commit();       // empty groups at the tail keep wait<2> arithmetic
        bufs = (bufs == 2) ? 0 : bufs + 1;
    }

    // ---- epilogue: g_part[ks][nout][batch]; c0/c1, c2/c3 batch-adjacent ----
    float* op = g_part + (long)ks * (NDIM * BATCH);
    int nout = mt * MTILE + wr + g;
#pragma unroll
    for (int q = 0; q < 4; q++) {
        int bcol = q * 8 + tg * 2;
        *(float2*)&op[(long)nout * BATCH + bcol]       = make_float2(acc[q][0], acc[q][1]);
        *(float2*)&op[(long)(nout + 8) * BATCH + bcol] = make_float2(acc[q][2], acc[q][3]);
    }
}

// ---------------------------------------------------------------------------
// Kernel 3: single-stage split-K reduce (32 -> 1) + bias + transpose.
// 16384 threads; 32 L2-resident loads each over 8 independent accumulators
// (MLP hides latency); fixed-order tree -> deterministic. Loads coalesced
// over i; the 64 KB scattered store is negligible.
// ---------------------------------------------------------------------------
__global__ __launch_bounds__(256) void reduce_kernel(const float* __restrict__ bias,
                                                     float* __restrict__ out)
{
    const int i = blockIdx.x * 256 + threadIdx.x;  // 0..16383 = nout*32 + b
    const int nout = i >> 5, b = i & 31;
    const int PL = NDIM * BATCH;

    float a0 = 0.f, a1 = 0.f, a2 = 0.f, a3 = 0.f;
    float a4 = 0.f, a5 = 0.f, a6 = 0.f, a7 = 0.f;
#pragma unroll
    for (int ks = 0; ks < KSPLIT; ks += 8) {
        a0 += g_part[(long)(ks + 0) * PL + i];
        a1 += g_part[(long)(ks + 1) * PL + i];
        a2 += g_part[(long)(ks + 2) * PL + i];
        a3 += g_part[(long)(ks + 3) * PL + i];
        a4 += g_part[(long)(ks + 4) * PL + i];
        a5 += g_part[(long)(ks + 5) * PL + i];
        a6 += g_part[(long)(ks + 6) * PL + i];
        a7 += g_part[(long)(ks + 7) * PL + i];
    }
    float s = (((a0 + a1) + (a2 + a3)) + ((a4 + a5) + (a6 + a7)));
    out[b * NDIM + nout] = s + bias[nout];
}

// ---------------------------------------------------------------------------
extern "C" void kernel_launch(void* const* d_in, const int* in_sizes, int n_in,
                              void* d_out, int out_size)
{
    const float* img    = (const float*)d_in[0];
    const float* weight = (const float*)d_in[1];
    const float* bias   = (const float*)d_in[2];
    float* out = (float*)d_out;

    cudaFuncSetAttribute(gemm_kernel,
                         cudaFuncAttributeMaxDynamicSharedMemorySize, SMEM_BYTES);

    feats_kernel<<<1024, 256>>>(img);
    gemm_kernel<<<dim3(4, KSPLIT), 256, SMEM_BYTES>>>(weight);
    reduce_kernel<<<(NDIM * BATCH) / 256, 256>>>(bias, out);
}